// round 3
// baseline (speedup 1.0000x reference)
#include <cuda_runtime.h>
#include <cuda_bf16.h>
#include <cstdint>

// ---------------------------------------------------------------------------
// GAT (4 layers) + FC on GB300.
//   - Detect edge_index dtype (JAX demotes int64->int32 without x64) at runtime.
//   - Build CSR grouped by destination once per launch (reused all 4 layers).
//   - Per layer: fused GEMM (h = x@W, alpha_s = h@a_src, alpha_d = h@a_dst),
//     then warp-per-node softmax aggregation (no float atomics).
// ---------------------------------------------------------------------------

#define MAXN 50176            // >= 50000, padded
#define MAXEL 1703936         // >= E + N = 1,650,000

__device__ float g_h0[(size_t)MAXN * 128];
__device__ float g_h1[(size_t)MAXN * 128];
__device__ float g_as[MAXN];
__device__ float g_ad[MAXN];
__device__ int   g_rp[MAXN + 1];
__device__ int   g_cnt[MAXN];
__device__ int   g_cur[MAXN];
__device__ int   g_col[MAXEL];
__device__ int   g_is64;

// ---------------------------------------------------------------------------
// Detect whether edge_index is int64 (odd 32-bit words all zero) or int32.
// ---------------------------------------------------------------------------
__global__ void detect_k(const int* __restrict__ ei_words) {
    int is64 = 1;
    for (int i = 1; i < 64; i += 2)
        if (ei_words[i] != 0) { is64 = 0; break; }
    g_is64 = is64;
}

__device__ __forceinline__ int load_idx(const void* ei, size_t pos) {
    if (g_is64) return (int)((const long long*)ei)[pos];
    return ((const int*)ei)[pos];
}

// ---------------------------------------------------------------------------
// CSR build
// ---------------------------------------------------------------------------
__global__ void zero_cnt_k(int* cnt, int n) {
    int i = blockIdx.x * blockDim.x + threadIdx.x;
    if (i < n) cnt[i] = 0;
}

__global__ void count_k(const void* __restrict__ ei, int E, int N, int* cnt) {
    int i = blockIdx.x * blockDim.x + threadIdx.x;
    int M = E + N;
    if (i >= M) return;
    int d = (i < E) ? load_idx(ei, (size_t)E + i) : (i - E);
    if (d < 0 || d >= N) d = 0;     // defensive: never fault
    atomicAdd(&cnt[d], 1);
}

// single-block scan over N counters -> row_ptr (exclusive) + cursor copy
__global__ void scan_k(const int* __restrict__ cnt, int* rp, int* cur, int n) {
    __shared__ int ss[1024];
    int tid = threadIdx.x;
    int chunk = (n + 1023) >> 10;
    int b = tid * chunk;
    int e = min(b + chunk, n);
    int s = 0;
    for (int i = b; i < e; ++i) s += cnt[i];
    ss[tid] = s;
    __syncthreads();
    for (int off = 1; off < 1024; off <<= 1) {
        int v = (tid >= off) ? ss[tid - off] : 0;
        __syncthreads();
        ss[tid] += v;
        __syncthreads();
    }
    int run = (tid > 0) ? ss[tid - 1] : 0;
    for (int i = b; i < e; ++i) {
        rp[i] = run;
        cur[i] = run;
        run += cnt[i];
    }
    if (tid == 1023) rp[n] = ss[1023];
}

__global__ void scatter_k(const void* __restrict__ ei, int E, int N,
                          int* cur, int* __restrict__ col) {
    int i = blockIdx.x * blockDim.x + threadIdx.x;
    int M = E + N;
    if (i >= M) return;
    int d, s;
    if (i < E) {
        d = load_idx(ei, (size_t)E + i);
        s = load_idx(ei, (size_t)i);
    } else {
        d = i - E;
        s = d;
    }
    if (d < 0 || d >= N) d = 0;
    if (s < 0 || s >= N) s = 0;
    int p = atomicAdd(&cur[d], 1);
    if (p >= 0 && p < MAXEL) col[p] = s;
}

// ---------------------------------------------------------------------------
// Fused GEMM: h = x @ W ; alpha_s = h @ a_src ; alpha_d = h @ a_dst
// Warp handles 4 rows; W chunk cached in smem; x row in registers via shfl.
// ---------------------------------------------------------------------------
template <int FIN, int FOUT, int KC>
__global__ void __launch_bounds__(256) gat_gemm_k(
    const float* __restrict__ x, const float* __restrict__ W,
    const float* __restrict__ avs, const float* __restrict__ avd,
    float* __restrict__ h, float* __restrict__ as_out, float* __restrict__ ad_out,
    int N)
{
    constexpr int VEC = FOUT / 32;   // features per lane
    constexpr int XR  = FIN / 32;    // x registers per row
    constexpr int NCH = FIN / KC;    // K chunks
    __shared__ float sW[KC * FOUT];

    const int warp = threadIdx.x >> 5;
    const int lane = threadIdx.x & 31;
    const int row0 = (blockIdx.x * 8 + warp) * 4;

    float xr[4][XR];
#pragma unroll
    for (int r = 0; r < 4; r++) {
        const float* xp = x + (size_t)(row0 + r) * FIN;
#pragma unroll
        for (int i = 0; i < XR; i++)
            xr[r][i] = (row0 + r < N) ? xp[lane + 32 * i] : 0.f;
    }

    float acc[4][VEC];
#pragma unroll
    for (int r = 0; r < 4; r++)
#pragma unroll
        for (int v = 0; v < VEC; v++) acc[r][v] = 0.f;

#pragma unroll
    for (int c = 0; c < NCH; c++) {
        __syncthreads();
        for (int i = threadIdx.x; i < KC * FOUT; i += 256)
            sW[i] = W[c * KC * FOUT + i];
        __syncthreads();
#pragma unroll
        for (int kk = 0; kk < KC; kk++) {
            const int k = c * KC + kk;
            float wv[VEC];
            const float* wp = sW + kk * FOUT + lane * VEC;
            if constexpr (VEC == 4) {
                float4 t = *(const float4*)wp;
                wv[0] = t.x; wv[1] = t.y; wv[2] = t.z; wv[3] = t.w;
            } else if constexpr (VEC == 2) {
                float2 t = *(const float2*)wp;
                wv[0] = t.x; wv[1] = t.y;
            } else {
                wv[0] = *wp;
            }
#pragma unroll
            for (int r = 0; r < 4; r++) {
                float xk = __shfl_sync(0xffffffffu, xr[r][k >> 5], k & 31);
#pragma unroll
                for (int v = 0; v < VEC; v++)
                    acc[r][v] = fmaf(xk, wv[v], acc[r][v]);
            }
        }
    }

    // epilogue: store h, compute alpha_s / alpha_d via warp reduction
    float av1[VEC], av2[VEC];
#pragma unroll
    for (int v = 0; v < VEC; v++) {
        av1[v] = avs[lane * VEC + v];
        av2[v] = avd[lane * VEC + v];
    }
#pragma unroll
    for (int r = 0; r < 4; r++) {
        int row = row0 + r;
        float s1 = 0.f, s2 = 0.f;
#pragma unroll
        for (int v = 0; v < VEC; v++) {
            s1 = fmaf(acc[r][v], av1[v], s1);
            s2 = fmaf(acc[r][v], av2[v], s2);
        }
#pragma unroll
        for (int off = 16; off; off >>= 1) {
            s1 += __shfl_xor_sync(0xffffffffu, s1, off);
            s2 += __shfl_xor_sync(0xffffffffu, s2, off);
        }
        if (row < N) {
            float* hp = h + (size_t)row * FOUT + lane * VEC;
            if constexpr (VEC == 4) {
                *(float4*)hp = make_float4(acc[r][0], acc[r][1], acc[r][2], acc[r][3]);
            } else if constexpr (VEC == 2) {
                *(float2*)hp = make_float2(acc[r][0], acc[r][1]);
            } else {
                *hp = acc[r][0];
            }
            if (lane == 0) { as_out[row] = s1; ad_out[row] = s2; }
        }
    }
}

// ---------------------------------------------------------------------------
// Softmax aggregation: warp per destination node.
// out[d] = relu( sum_e softmax(e) * h[src_e] + bias )
// ---------------------------------------------------------------------------
template <int FOUT>
__global__ void __launch_bounds__(256) gat_agg_k(
    const int* __restrict__ rp, const int* __restrict__ col,
    const float* __restrict__ h, const float* __restrict__ as,
    const float* __restrict__ ad, const float* __restrict__ bias,
    float* __restrict__ out, int N)
{
    constexpr int VEC = FOUT / 32;
    int node = blockIdx.x * 8 + (threadIdx.x >> 5);
    if (node >= N) return;
    int lane = threadIdx.x & 31;
    int beg = rp[node], end = rp[node + 1];
    float add = ad[node];

    // pass 1: max over edges (lane-strided)
    float m = -1e30f;
    for (int j = beg + lane; j < end; j += 32) {
        float e = as[col[j]] + add;
        e = e > 0.f ? e : 0.2f * e;
        m = fmaxf(m, e);
    }
#pragma unroll
    for (int off = 16; off; off >>= 1)
        m = fmaxf(m, __shfl_xor_sync(0xffffffffu, m, off));

    // pass 2: weighted accumulation (all lanes walk edges together)
    float acc[VEC];
#pragma unroll
    for (int v = 0; v < VEC; v++) acc[v] = 0.f;
    float s = 0.f;
    for (int j = beg; j < end; ++j) {
        int src = col[j];
        float e = as[src] + add;
        e = e > 0.f ? e : 0.2f * e;
        float w = __expf(e - m);
        s += w;
        const float* hp = h + (size_t)src * FOUT + lane * VEC;
        if constexpr (VEC == 4) {
            float4 t = *(const float4*)hp;
            acc[0] = fmaf(w, t.x, acc[0]);
            acc[1] = fmaf(w, t.y, acc[1]);
            acc[2] = fmaf(w, t.z, acc[2]);
            acc[3] = fmaf(w, t.w, acc[3]);
        } else if constexpr (VEC == 2) {
            float2 t = *(const float2*)hp;
            acc[0] = fmaf(w, t.x, acc[0]);
            acc[1] = fmaf(w, t.y, acc[1]);
        } else {
            acc[0] = fmaf(w, *hp, acc[0]);
        }
    }
    float inv = 1.f / s;
    float* op = out + (size_t)node * FOUT + lane * VEC;
#pragma unroll
    for (int v = 0; v < VEC; v++) {
        float r = acc[v] * inv + bias[lane * VEC + v];
        op[v] = fmaxf(r, 0.f);
    }
}

// ---------------------------------------------------------------------------
// Final FC: out = x @ fc_W + fc_b   ([N,128] @ [128,16])
// ---------------------------------------------------------------------------
__global__ void __launch_bounds__(256) fc_k(
    const float* __restrict__ x, const float* __restrict__ W,
    const float* __restrict__ b, float* __restrict__ out, int N)
{
    __shared__ float sW[128 * 16];
    for (int i = threadIdx.x; i < 128 * 16; i += 256) sW[i] = W[i];
    __syncthreads();
    int warp = threadIdx.x >> 5, lane = threadIdx.x & 31;
    int row = blockIdx.x * 8 + warp;
    float xr[4];
    const float* xp = x + (size_t)row * 128;
#pragma unroll
    for (int i = 0; i < 4; i++) xr[i] = (row < N) ? xp[lane + 32 * i] : 0.f;
    float acc = 0.f;
#pragma unroll
    for (int k = 0; k < 128; k++) {
        float xk = __shfl_sync(0xffffffffu, xr[k >> 5], k & 31);
        acc = fmaf(xk, sW[k * 16 + (lane & 15)], acc);
    }
    if (row < N && lane < 16) out[(size_t)row * 16 + lane] = acc + b[lane];
}

// ---------------------------------------------------------------------------
// Host launcher
// ---------------------------------------------------------------------------
extern "C" void kernel_launch(void* const* d_in, const int* in_sizes, int n_in,
                              void* d_out, int out_size)
{
    const float* x   = (const float*)d_in[0];
    const void*  ei  = d_in[1];
    const float* W[4]  = {(const float*)d_in[2],  (const float*)d_in[6],
                          (const float*)d_in[10], (const float*)d_in[14]};
    const float* As[4] = {(const float*)d_in[3],  (const float*)d_in[7],
                          (const float*)d_in[11], (const float*)d_in[15]};
    const float* Ad[4] = {(const float*)d_in[4],  (const float*)d_in[8],
                          (const float*)d_in[12], (const float*)d_in[16]};
    const float* B[4]  = {(const float*)d_in[5],  (const float*)d_in[9],
                          (const float*)d_in[13], (const float*)d_in[17]};
    const float* fcW = (const float*)d_in[18];
    const float* fcB = (const float*)d_in[19];

    int N = in_sizes[0] / 128;
    int E = in_sizes[1] / 2;
    int M = E + N;

    float *h0, *h1, *as_, *ad_;
    int *rp, *cnt, *cur, *col;
    cudaGetSymbolAddress((void**)&h0,  g_h0);
    cudaGetSymbolAddress((void**)&h1,  g_h1);
    cudaGetSymbolAddress((void**)&as_, g_as);
    cudaGetSymbolAddress((void**)&ad_, g_ad);
    cudaGetSymbolAddress((void**)&rp,  g_rp);
    cudaGetSymbolAddress((void**)&cnt, g_cnt);
    cudaGetSymbolAddress((void**)&cur, g_cur);
    cudaGetSymbolAddress((void**)&col, g_col);

    // --- dtype sniff + CSR build (grouped by dst, reused for all 4 layers) ---
    detect_k<<<1, 1>>>((const int*)ei);
    zero_cnt_k<<<(N + 255) / 256, 256>>>(cnt, N);
    count_k<<<(M + 255) / 256, 256>>>(ei, E, N, cnt);
    scan_k<<<1, 1024>>>(cnt, rp, cur, N);
    scatter_k<<<(M + 255) / 256, 256>>>(ei, E, N, cur, col);

    int gemm_grid = (N + 31) / 32;
    int agg_grid  = (N + 7) / 8;

    // --- Layer 0: 128 -> 32 ---
    gat_gemm_k<128, 32, 64><<<gemm_grid, 256>>>(x, W[0], As[0], Ad[0], h0, as_, ad_, N);
    gat_agg_k<32><<<agg_grid, 256>>>(rp, col, h0, as_, ad_, B[0], h1, N);

    // --- Layer 1: 32 -> 64 ---
    gat_gemm_k<32, 64, 32><<<gemm_grid, 256>>>(h1, W[1], As[1], Ad[1], h0, as_, ad_, N);
    gat_agg_k<64><<<agg_grid, 256>>>(rp, col, h0, as_, ad_, B[1], h1, N);

    // --- Layer 2: 64 -> 128 ---
    gat_gemm_k<64, 128, 64><<<gemm_grid, 256>>>(h1, W[2], As[2], Ad[2], h0, as_, ad_, N);
    gat_agg_k<128><<<agg_grid, 256>>>(rp, col, h0, as_, ad_, B[2], h1, N);

    // --- Layer 3: 128 -> 128 ---
    gat_gemm_k<128, 128, 64><<<gemm_grid, 256>>>(h1, W[3], As[3], Ad[3], h0, as_, ad_, N);
    gat_agg_k<128><<<agg_grid, 256>>>(rp, col, h0, as_, ad_, B[3], h1, N);

    // --- FC: 128 -> 16 ---
    fc_k<<<agg_grid, 256>>>(h1, fcW, fcB, (float*)d_out, N);
}

// round 5
// speedup vs baseline: 1.1496x; 1.1496x over previous
#include <cuda_runtime.h>
#include <cuda_bf16.h>
#include <cstdint>

// ---------------------------------------------------------------------------
// GAT (4 layers) + FC on GB300.
//   - Warp-parallel edge_index dtype detect (JAX demotes int64->int32).
//   - CSR by destination built once, fast 3-kernel scan.
//   - Per layer: fused GEMM (h = x@W + attention score epilogue),
//     warp-per-node softmax aggregation with x4-unrolled edge loop.
// ---------------------------------------------------------------------------

#define MAXN 50176            // >= 50000, padded (multiple of 256)
#define MAXEL 1703936         // >= E + N
#define SCANB 256             // elements per scan block

__device__ float g_h0[(size_t)MAXN * 128];
__device__ float g_h1[(size_t)MAXN * 128];
__device__ float g_as[MAXN];
__device__ float g_ad[MAXN];
__device__ int   g_rp[MAXN + 1];
__device__ int   g_cnt[MAXN];
__device__ int   g_cur[MAXN];
__device__ int   g_col[MAXEL];
__device__ int   g_psum[MAXN / SCANB + 1];
__device__ int   g_is64;

// ---------------------------------------------------------------------------
// dtype detect: int64 edge_index has all-odd-32b-words == 0 (values < 2^31).
// ---------------------------------------------------------------------------
__global__ void detect_k(const int* __restrict__ w) {
    int lane = threadIdx.x;
    int bad = (w[lane * 2 + 1] != 0);
    unsigned any = __ballot_sync(0xffffffffu, bad);
    if (lane == 0) g_is64 = (any == 0u);
}

__device__ __forceinline__ int load_idx(const void* ei, size_t pos) {
    if (g_is64) return (int)((const long long*)ei)[pos];
    return ((const int*)ei)[pos];
}

// ---------------------------------------------------------------------------
// CSR build
// ---------------------------------------------------------------------------
__global__ void zero_cnt_k(int* cnt, int n) {
    int i = blockIdx.x * blockDim.x + threadIdx.x;
    if (i < n) cnt[i] = 0;
}

__global__ void count_k(const void* __restrict__ ei, int E, int N, int* cnt) {
    int i = blockIdx.x * blockDim.x + threadIdx.x;
    int M = E + N;
    if (i >= M) return;
    int d = (i < E) ? load_idx(ei, (size_t)E + i) : (i - E);
    if (d < 0 || d >= N) d = 0;
    atomicAdd(&cnt[d], 1);
}

// scan stage 1: per-block (256-elem) sums
__global__ void scan1_k(const int* __restrict__ cnt, int* psum, int n) {
    __shared__ int ss[8];
    int i = blockIdx.x * SCANB + threadIdx.x;
    int v = (i < n) ? cnt[i] : 0;
#pragma unroll
    for (int off = 16; off; off >>= 1) v += __shfl_xor_sync(0xffffffffu, v, off);
    if ((threadIdx.x & 31) == 0) ss[threadIdx.x >> 5] = v;
    __syncthreads();
    if (threadIdx.x == 0) {
        int t = 0;
#pragma unroll
        for (int k = 0; k < 8; k++) t += ss[k];
        psum[blockIdx.x] = t;
    }
}

// scan stage 2: exclusive scan of nb (<=256) partials, one block; writes rp[n]
__global__ void scan2_k(int* psum, int nb, int* rp, int n) {
    __shared__ int ss[SCANB];
    int tid = threadIdx.x;
    int v = (tid < nb) ? psum[tid] : 0;
    ss[tid] = v;
    __syncthreads();
#pragma unroll
    for (int off = 1; off < SCANB; off <<= 1) {
        int t = (tid >= off) ? ss[tid - off] : 0;
        __syncthreads();
        ss[tid] += t;
        __syncthreads();
    }
    if (tid < nb) psum[tid] = ss[tid] - v;      // exclusive
    if (tid == SCANB - 1) rp[n] = ss[SCANB - 1];
}

// scan stage 3: per-block exclusive scan + block offset -> rp, cur
__global__ void scan3_k(const int* __restrict__ cnt, const int* __restrict__ psum,
                        int* rp, int* cur, int n) {
    __shared__ int ss[SCANB];
    int tid = threadIdx.x;
    int i = blockIdx.x * SCANB + tid;
    int v = (i < n) ? cnt[i] : 0;
    ss[tid] = v;
    __syncthreads();
#pragma unroll
    for (int off = 1; off < SCANB; off <<= 1) {
        int t = (tid >= off) ? ss[tid - off] : 0;
        __syncthreads();
        ss[tid] += t;
        __syncthreads();
    }
    if (i < n) {
        int r = ss[tid] - v + psum[blockIdx.x];
        rp[i] = r;
        cur[i] = r;
    }
}

__global__ void scatter_k(const void* __restrict__ ei, int E, int N,
                          int* cur, int* __restrict__ col) {
    int i = blockIdx.x * blockDim.x + threadIdx.x;
    int M = E + N;
    if (i >= M) return;
    int d, s;
    if (i < E) {
        d = load_idx(ei, (size_t)E + i);
        s = load_idx(ei, (size_t)i);
    } else {
        d = i - E;
        s = d;
    }
    if (d < 0 || d >= N) d = 0;
    if (s < 0 || s >= N) s = 0;
    int p = atomicAdd(&cur[d], 1);
    if (p >= 0 && p < MAXEL) col[p] = s;
}

// ---------------------------------------------------------------------------
// Fused GEMM: h = x @ W ; alpha_s = h @ a_src ; alpha_d = h @ a_dst
// ---------------------------------------------------------------------------
template <int FIN, int FOUT, int KC>
__global__ void __launch_bounds__(256) gat_gemm_k(
    const float* __restrict__ x, const float* __restrict__ W,
    const float* __restrict__ avs, const float* __restrict__ avd,
    float* __restrict__ h, float* __restrict__ as_out, float* __restrict__ ad_out,
    int N)
{
    constexpr int VEC = FOUT / 32;
    constexpr int XR  = FIN / 32;
    constexpr int NCH = FIN / KC;
    __shared__ float sW[KC * FOUT];

    const int warp = threadIdx.x >> 5;
    const int lane = threadIdx.x & 31;
    const int row0 = (blockIdx.x * 8 + warp) * 4;

    float xr[4][XR];
#pragma unroll
    for (int r = 0; r < 4; r++) {
        const float* xp = x + (size_t)(row0 + r) * FIN;
#pragma unroll
        for (int i = 0; i < XR; i++)
            xr[r][i] = (row0 + r < N) ? xp[lane + 32 * i] : 0.f;
    }

    float acc[4][VEC];
#pragma unroll
    for (int r = 0; r < 4; r++)
#pragma unroll
        for (int v = 0; v < VEC; v++) acc[r][v] = 0.f;

#pragma unroll
    for (int c = 0; c < NCH; c++) {
        __syncthreads();
        for (int i = threadIdx.x; i < KC * FOUT; i += 256)
            sW[i] = W[c * KC * FOUT + i];
        __syncthreads();
#pragma unroll
        for (int kk = 0; kk < KC; kk++) {
            const int k = c * KC + kk;
            float wv[VEC];
            const float* wp = sW + kk * FOUT + lane * VEC;
            if constexpr (VEC == 4) {
                float4 t = *(const float4*)wp;
                wv[0] = t.x; wv[1] = t.y; wv[2] = t.z; wv[3] = t.w;
            } else if constexpr (VEC == 2) {
                float2 t = *(const float2*)wp;
                wv[0] = t.x; wv[1] = t.y;
            } else {
                wv[0] = *wp;
            }
#pragma unroll
            for (int r = 0; r < 4; r++) {
                float xk = __shfl_sync(0xffffffffu, xr[r][k >> 5], k & 31);
#pragma unroll
                for (int v = 0; v < VEC; v++)
                    acc[r][v] = fmaf(xk, wv[v], acc[r][v]);
            }
        }
    }

    float av1[VEC], av2[VEC];
#pragma unroll
    for (int v = 0; v < VEC; v++) {
        av1[v] = avs[lane * VEC + v];
        av2[v] = avd[lane * VEC + v];
    }
#pragma unroll
    for (int r = 0; r < 4; r++) {
        int row = row0 + r;
        float s1 = 0.f, s2 = 0.f;
#pragma unroll
        for (int v = 0; v < VEC; v++) {
            s1 = fmaf(acc[r][v], av1[v], s1);
            s2 = fmaf(acc[r][v], av2[v], s2);
        }
#pragma unroll
        for (int off = 16; off; off >>= 1) {
            s1 += __shfl_xor_sync(0xffffffffu, s1, off);
            s2 += __shfl_xor_sync(0xffffffffu, s2, off);
        }
        if (row < N) {
            float* hp = h + (size_t)row * FOUT + lane * VEC;
            if constexpr (VEC == 4) {
                *(float4*)hp = make_float4(acc[r][0], acc[r][1], acc[r][2], acc[r][3]);
            } else if constexpr (VEC == 2) {
                *(float2*)hp = make_float2(acc[r][0], acc[r][1]);
            } else {
                *hp = acc[r][0];
            }
            if (lane == 0) { as_out[row] = s1; ad_out[row] = s2; }
        }
    }
}

// ---------------------------------------------------------------------------
// Softmax aggregation: warp per destination node, edge loop unrolled x4.
// ---------------------------------------------------------------------------
__device__ __forceinline__ float lrelu(float e) { return e > 0.f ? e : 0.2f * e; }

template <int FOUT>
__global__ void __launch_bounds__(256) gat_agg_k(
    const int* __restrict__ rp, const int* __restrict__ col,
    const float* __restrict__ h, const float* __restrict__ as,
    const float* __restrict__ ad, const float* __restrict__ bias,
    float* __restrict__ out, int N)
{
    constexpr int VEC = FOUT / 32;
    int node = blockIdx.x * 8 + (threadIdx.x >> 5);
    if (node >= N) return;
    int lane = threadIdx.x & 31;
    int beg = rp[node], end = rp[node + 1];
    float add = ad[node];

    // pass 1: max (lane-strided)
    float m = -1e30f;
    for (int j = beg + lane; j < end; j += 32)
        m = fmaxf(m, lrelu(as[col[j]] + add));
#pragma unroll
    for (int off = 16; off; off >>= 1)
        m = fmaxf(m, __shfl_xor_sync(0xffffffffu, m, off));

    // pass 2: weighted accumulation, unrolled x4 for gather MLP
    float acc[VEC];
#pragma unroll
    for (int v = 0; v < VEC; v++) acc[v] = 0.f;
    float s = 0.f;
    int j = beg;
    for (; j + 4 <= end; j += 4) {
        int s0 = col[j], s1 = col[j + 1], s2 = col[j + 2], s3 = col[j + 3];
        float w0 = __expf(lrelu(as[s0] + add) - m);
        float w1 = __expf(lrelu(as[s1] + add) - m);
        float w2 = __expf(lrelu(as[s2] + add) - m);
        float w3 = __expf(lrelu(as[s3] + add) - m);
        s += (w0 + w1) + (w2 + w3);
        const float* p0 = h + (size_t)s0 * FOUT + lane * VEC;
        const float* p1 = h + (size_t)s1 * FOUT + lane * VEC;
        const float* p2 = h + (size_t)s2 * FOUT + lane * VEC;
        const float* p3 = h + (size_t)s3 * FOUT + lane * VEC;
        if constexpr (VEC == 4) {
            float4 t0 = *(const float4*)p0;
            float4 t1 = *(const float4*)p1;
            float4 t2 = *(const float4*)p2;
            float4 t3 = *(const float4*)p3;
            acc[0] = fmaf(w0, t0.x, acc[0]); acc[1] = fmaf(w0, t0.y, acc[1]);
            acc[2] = fmaf(w0, t0.z, acc[2]); acc[3] = fmaf(w0, t0.w, acc[3]);
            acc[0] = fmaf(w1, t1.x, acc[0]); acc[1] = fmaf(w1, t1.y, acc[1]);
            acc[2] = fmaf(w1, t1.z, acc[2]); acc[3] = fmaf(w1, t1.w, acc[3]);
            acc[0] = fmaf(w2, t2.x, acc[0]); acc[1] = fmaf(w2, t2.y, acc[1]);
            acc[2] = fmaf(w2, t2.z, acc[2]); acc[3] = fmaf(w2, t2.w, acc[3]);
            acc[0] = fmaf(w3, t3.x, acc[0]); acc[1] = fmaf(w3, t3.y, acc[1]);
            acc[2] = fmaf(w3, t3.z, acc[2]); acc[3] = fmaf(w3, t3.w, acc[3]);
        } else if constexpr (VEC == 2) {
            float2 t0 = *(const float2*)p0;
            float2 t1 = *(const float2*)p1;
            float2 t2 = *(const float2*)p2;
            float2 t3 = *(const float2*)p3;
            acc[0] = fmaf(w0, t0.x, acc[0]); acc[1] = fmaf(w0, t0.y, acc[1]);
            acc[0] = fmaf(w1, t1.x, acc[0]); acc[1] = fmaf(w1, t1.y, acc[1]);
            acc[0] = fmaf(w2, t2.x, acc[0]); acc[1] = fmaf(w2, t2.y, acc[1]);
            acc[0] = fmaf(w3, t3.x, acc[0]); acc[1] = fmaf(w3, t3.y, acc[1]);
        } else {
            float t0 = *p0, t1 = *p1, t2 = *p2, t3 = *p3;
            acc[0] = fmaf(w0, t0, acc[0]);
            acc[0] = fmaf(w1, t1, acc[0]);
            acc[0] = fmaf(w2, t2, acc[0]);
            acc[0] = fmaf(w3, t3, acc[0]);
        }
    }
    for (; j < end; ++j) {
        int src = col[j];
        float w = __expf(lrelu(as[src] + add) - m);
        s += w;
        const float* hp = h + (size_t)src * FOUT + lane * VEC;
#pragma unroll
        for (int v = 0; v < VEC; v++)
            acc[v] = fmaf(w, hp[v], acc[v]);
    }

    float inv = 1.f / s;
    float* op = out + (size_t)node * FOUT + lane * VEC;
#pragma unroll
    for (int v = 0; v < VEC; v++)
        op[v] = fmaxf(acc[v] * inv + bias[lane * VEC + v], 0.f);
}

// ---------------------------------------------------------------------------
// Final FC: out = x @ fc_W + fc_b   ([N,128] @ [128,16])
// ---------------------------------------------------------------------------
__global__ void __launch_bounds__(256) fc_k(
    const float* __restrict__ x, const float* __restrict__ W,
    const float* __restrict__ b, float* __restrict__ out, int N)
{
    __shared__ float sW[128 * 16];
    for (int i = threadIdx.x; i < 128 * 16; i += 256) sW[i] = W[i];
    __syncthreads();
    int warp = threadIdx.x >> 5, lane = threadIdx.x & 31;
    int row = blockIdx.x * 8 + warp;
    float xr[4];
    const float* xp = x + (size_t)row * 128;
#pragma unroll
    for (int i = 0; i < 4; i++) xr[i] = (row < N) ? xp[lane + 32 * i] : 0.f;
    float acc = 0.f;
#pragma unroll
    for (int k = 0; k < 128; k++) {
        float xk = __shfl_sync(0xffffffffu, xr[k >> 5], k & 31);
        acc = fmaf(xk, sW[k * 16 + (lane & 15)], acc);
    }
    if (row < N && lane < 16) out[(size_t)row * 16 + lane] = acc + b[lane];
}

// ---------------------------------------------------------------------------
// Host launcher
// ---------------------------------------------------------------------------
extern "C" void kernel_launch(void* const* d_in, const int* in_sizes, int n_in,
                              void* d_out, int out_size)
{
    const float* x   = (const float*)d_in[0];
    const void*  ei  = d_in[1];
    const float* W[4]  = {(const float*)d_in[2],  (const float*)d_in[6],
                          (const float*)d_in[10], (const float*)d_in[14]};
    const float* As[4] = {(const float*)d_in[3],  (const float*)d_in[7],
                          (const float*)d_in[11], (const float*)d_in[15]};
    const float* Ad[4] = {(const float*)d_in[4],  (const float*)d_in[8],
                          (const float*)d_in[12], (const float*)d_in[16]};
    const float* B[4]  = {(const float*)d_in[5],  (const float*)d_in[9],
                          (const float*)d_in[13], (const float*)d_in[17]};
    const float* fcW = (const float*)d_in[18];
    const float* fcB = (const float*)d_in[19];

    int N = in_sizes[0] / 128;
    int E = in_sizes[1] / 2;
    int M = E + N;
    int nb = (N + SCANB - 1) / SCANB;

    float *h0, *h1, *as_, *ad_;
    int *rp, *cnt, *cur, *col, *psum;
    cudaGetSymbolAddress((void**)&h0,   g_h0);
    cudaGetSymbolAddress((void**)&h1,   g_h1);
    cudaGetSymbolAddress((void**)&as_,  g_as);
    cudaGetSymbolAddress((void**)&ad_,  g_ad);
    cudaGetSymbolAddress((void**)&rp,   g_rp);
    cudaGetSymbolAddress((void**)&cnt,  g_cnt);
    cudaGetSymbolAddress((void**)&cur,  g_cur);
    cudaGetSymbolAddress((void**)&col,  g_col);
    cudaGetSymbolAddress((void**)&psum, g_psum);

    // --- dtype sniff + CSR build ---
    detect_k<<<1, 32>>>((const int*)ei);
    zero_cnt_k<<<(N + 255) / 256, 256>>>(cnt, N);
    count_k<<<(M + 255) / 256, 256>>>(ei, E, N, cnt);
    scan1_k<<<nb, SCANB>>>(cnt, psum, N);
    scan2_k<<<1, SCANB>>>(psum, nb, rp, N);
    scan3_k<<<nb, SCANB>>>(cnt, psum, rp, cur, N);
    scatter_k<<<(M + 255) / 256, 256>>>(ei, E, N, cur, col);

    int gemm_grid = (N + 31) / 32;
    int agg_grid  = (N + 7) / 8;

    // --- Layer 0: 128 -> 32 ---
    gat_gemm_k<128, 32, 64><<<gemm_grid, 256>>>(x, W[0], As[0], Ad[0], h0, as_, ad_, N);
    gat_agg_k<32><<<agg_grid, 256>>>(rp, col, h0, as_, ad_, B[0], h1, N);

    // --- Layer 1: 32 -> 64 ---
    gat_gemm_k<32, 64, 32><<<gemm_grid, 256>>>(h1, W[1], As[1], Ad[1], h0, as_, ad_, N);
    gat_agg_k<64><<<agg_grid, 256>>>(rp, col, h0, as_, ad_, B[1], h1, N);

    // --- Layer 2: 64 -> 128 ---
    gat_gemm_k<64, 128, 64><<<gemm_grid, 256>>>(h1, W[2], As[2], Ad[2], h0, as_, ad_, N);
    gat_agg_k<128><<<agg_grid, 256>>>(rp, col, h0, as_, ad_, B[2], h1, N);

    // --- Layer 3: 128 -> 128 ---
    gat_gemm_k<128, 128, 64><<<gemm_grid, 256>>>(h1, W[3], As[3], Ad[3], h0, as_, ad_, N);
    gat_agg_k<128><<<agg_grid, 256>>>(rp, col, h0, as_, ad_, B[3], h1, N);

    // --- FC: 128 -> 16 ---
    fc_k<<<agg_grid, 256>>>(h1, fcW, fcB, (float*)d_out, N);
}

// round 6
// speedup vs baseline: 1.1787x; 1.0253x over previous
#include <cuda_runtime.h>
#include <cuda_bf16.h>
#include <cstdint>

// ---------------------------------------------------------------------------
// GAT (4 layers) + FC on GB300.
//   - CSR by destination built once (fast 3-stage scan).
//   - Scores via precomputed u = W@a vectors (associativity) where useful.
//   - Aggregate on the cheaper side of the GEMM (min(FIN,FOUT) features/edge).
//   - Softmax stabilized by the self-loop score: no segment-max pass.
// ---------------------------------------------------------------------------

#define MAXN 50176            // >= 50000, padded (multiple of 256)
#define MAXEL 1703936         // >= E + N
#define SCANB 256

__device__ float g_h0[(size_t)MAXN * 128];
__device__ float g_h1[(size_t)MAXN * 128];
__device__ float g_as[MAXN];
__device__ float g_ad[MAXN];
__device__ float g_us[128];
__device__ float g_ud[128];
__device__ int   g_rp[MAXN + 1];
__device__ int   g_cnt[MAXN];
__device__ int   g_cur[MAXN];
__device__ int   g_col[MAXEL];
__device__ int   g_psum[MAXN / SCANB + 1];
__device__ int   g_is64;

// ---------------------------------------------------------------------------
// dtype detect (JAX demotes int64->int32 without x64)
// ---------------------------------------------------------------------------
__global__ void detect_k(const int* __restrict__ w) {
    int lane = threadIdx.x;
    int bad = (w[lane * 2 + 1] != 0);
    unsigned any = __ballot_sync(0xffffffffu, bad);
    if (lane == 0) g_is64 = (any == 0u);
}

__device__ __forceinline__ int load_idx(const void* ei, size_t pos) {
    if (g_is64) return (int)((const long long*)ei)[pos];
    return ((const int*)ei)[pos];
}

// ---------------------------------------------------------------------------
// CSR build
// ---------------------------------------------------------------------------
__global__ void zero_cnt_k(int* cnt, int n) {
    int i = blockIdx.x * blockDim.x + threadIdx.x;
    if (i < n) cnt[i] = 0;
}

__global__ void count_k(const void* __restrict__ ei, int E, int N, int* cnt) {
    int i = blockIdx.x * blockDim.x + threadIdx.x;
    int M = E + N;
    if (i >= M) return;
    int d = (i < E) ? load_idx(ei, (size_t)E + i) : (i - E);
    if (d < 0 || d >= N) d = 0;
    atomicAdd(&cnt[d], 1);
}

__global__ void scan1_k(const int* __restrict__ cnt, int* psum, int n) {
    __shared__ int ss[8];
    int i = blockIdx.x * SCANB + threadIdx.x;
    int v = (i < n) ? cnt[i] : 0;
#pragma unroll
    for (int off = 16; off; off >>= 1) v += __shfl_xor_sync(0xffffffffu, v, off);
    if ((threadIdx.x & 31) == 0) ss[threadIdx.x >> 5] = v;
    __syncthreads();
    if (threadIdx.x == 0) {
        int t = 0;
#pragma unroll
        for (int k = 0; k < 8; k++) t += ss[k];
        psum[blockIdx.x] = t;
    }
}

__global__ void scan2_k(int* psum, int nb, int* rp, int n) {
    __shared__ int ss[SCANB];
    int tid = threadIdx.x;
    int v = (tid < nb) ? psum[tid] : 0;
    ss[tid] = v;
    __syncthreads();
#pragma unroll
    for (int off = 1; off < SCANB; off <<= 1) {
        int t = (tid >= off) ? ss[tid - off] : 0;
        __syncthreads();
        ss[tid] += t;
        __syncthreads();
    }
    if (tid < nb) psum[tid] = ss[tid] - v;
    if (tid == SCANB - 1) rp[n] = ss[SCANB - 1];
}

__global__ void scan3_k(const int* __restrict__ cnt, const int* __restrict__ psum,
                        int* rp, int* cur, int n) {
    __shared__ int ss[SCANB];
    int tid = threadIdx.x;
    int i = blockIdx.x * SCANB + tid;
    int v = (i < n) ? cnt[i] : 0;
    ss[tid] = v;
    __syncthreads();
#pragma unroll
    for (int off = 1; off < SCANB; off <<= 1) {
        int t = (tid >= off) ? ss[tid - off] : 0;
        __syncthreads();
        ss[tid] += t;
        __syncthreads();
    }
    if (i < n) {
        int r = ss[tid] - v + psum[blockIdx.x];
        rp[i] = r;
        cur[i] = r;
    }
}

__global__ void scatter_k(const void* __restrict__ ei, int E, int N,
                          int* cur, int* __restrict__ col) {
    int i = blockIdx.x * blockDim.x + threadIdx.x;
    int M = E + N;
    if (i >= M) return;
    int d, s;
    if (i < E) {
        d = load_idx(ei, (size_t)E + i);
        s = load_idx(ei, (size_t)i);
    } else {
        d = i - E;
        s = d;
    }
    if (d < 0 || d >= N) d = 0;
    if (s < 0 || s >= N) s = 0;
    int p = atomicAdd(&cur[d], 1);
    if (p >= 0 && p < MAXEL) col[p] = s;
}

// ---------------------------------------------------------------------------
// u = W @ a  (tiny: FIN x FOUT @ FOUT). One block.
// ---------------------------------------------------------------------------
template <int FIN, int FOUT>
__global__ void wa_k(const float* __restrict__ W, const float* __restrict__ a_s,
                     const float* __restrict__ a_d,
                     float* __restrict__ us, float* __restrict__ ud) {
    int i = threadIdx.x;
    if (i >= FIN) return;
    float s1 = 0.f, s2 = 0.f;
#pragma unroll 4
    for (int j = 0; j < FOUT; j++) {
        float w = W[i * FOUT + j];
        s1 = fmaf(w, a_s[j], s1);
        s2 = fmaf(w, a_d[j], s2);
    }
    us[i] = s1;
    ud[i] = s2;
}

// ---------------------------------------------------------------------------
// Scores: alpha_s[n] = x[n,:]@us, alpha_d[n] = x[n,:]@ud. Warp per row.
// ---------------------------------------------------------------------------
template <int F>
__global__ void __launch_bounds__(256) score_k(
    const float* __restrict__ x, const float* __restrict__ us,
    const float* __restrict__ ud, float* __restrict__ as_out,
    float* __restrict__ ad_out, int N)
{
    int node = blockIdx.x * 8 + (threadIdx.x >> 5);
    if (node >= N) return;
    int lane = threadIdx.x & 31;
    const float* xp = x + (size_t)node * F;
    float s1 = 0.f, s2 = 0.f;
#pragma unroll
    for (int i = lane; i < F; i += 32) {
        float xv = xp[i];
        s1 = fmaf(xv, us[i], s1);
        s2 = fmaf(xv, ud[i], s2);
    }
#pragma unroll
    for (int off = 16; off; off >>= 1) {
        s1 += __shfl_xor_sync(0xffffffffu, s1, off);
        s2 += __shfl_xor_sync(0xffffffffu, s2, off);
    }
    if (lane == 0) { as_out[node] = s1; ad_out[node] = s2; }
}

// ---------------------------------------------------------------------------
// Fused GEMM: h = x @ W ; alpha_s = h @ a_src ; alpha_d = h @ a_dst
// ---------------------------------------------------------------------------
template <int FIN, int FOUT, int KC>
__global__ void __launch_bounds__(256) gat_gemm_k(
    const float* __restrict__ x, const float* __restrict__ W,
    const float* __restrict__ avs, const float* __restrict__ avd,
    float* __restrict__ h, float* __restrict__ as_out, float* __restrict__ ad_out,
    int N)
{
    constexpr int VEC = FOUT / 32;
    constexpr int XR  = FIN / 32;
    constexpr int NCH = FIN / KC;
    __shared__ float sW[KC * FOUT];

    const int warp = threadIdx.x >> 5;
    const int lane = threadIdx.x & 31;
    const int row0 = (blockIdx.x * 8 + warp) * 4;

    float xr[4][XR];
#pragma unroll
    for (int r = 0; r < 4; r++) {
        const float* xp = x + (size_t)(row0 + r) * FIN;
#pragma unroll
        for (int i = 0; i < XR; i++)
            xr[r][i] = (row0 + r < N) ? xp[lane + 32 * i] : 0.f;
    }

    float acc[4][VEC];
#pragma unroll
    for (int r = 0; r < 4; r++)
#pragma unroll
        for (int v = 0; v < VEC; v++) acc[r][v] = 0.f;

#pragma unroll
    for (int c = 0; c < NCH; c++) {
        __syncthreads();
        for (int i = threadIdx.x; i < KC * FOUT; i += 256)
            sW[i] = W[c * KC * FOUT + i];
        __syncthreads();
#pragma unroll
        for (int kk = 0; kk < KC; kk++) {
            const int k = c * KC + kk;
            float wv[VEC];
            const float* wp = sW + kk * FOUT + lane * VEC;
            if constexpr (VEC == 4) {
                float4 t = *(const float4*)wp;
                wv[0] = t.x; wv[1] = t.y; wv[2] = t.z; wv[3] = t.w;
            } else if constexpr (VEC == 2) {
                float2 t = *(const float2*)wp;
                wv[0] = t.x; wv[1] = t.y;
            } else {
                wv[0] = *wp;
            }
#pragma unroll
            for (int r = 0; r < 4; r++) {
                float xk = __shfl_sync(0xffffffffu, xr[r][k >> 5], k & 31);
#pragma unroll
                for (int v = 0; v < VEC; v++)
                    acc[r][v] = fmaf(xk, wv[v], acc[r][v]);
            }
        }
    }

    float av1[VEC], av2[VEC];
#pragma unroll
    for (int v = 0; v < VEC; v++) {
        av1[v] = avs[lane * VEC + v];
        av2[v] = avd[lane * VEC + v];
    }
#pragma unroll
    for (int r = 0; r < 4; r++) {
        int row = row0 + r;
        float s1 = 0.f, s2 = 0.f;
#pragma unroll
        for (int v = 0; v < VEC; v++) {
            s1 = fmaf(acc[r][v], av1[v], s1);
            s2 = fmaf(acc[r][v], av2[v], s2);
        }
#pragma unroll
        for (int off = 16; off; off >>= 1) {
            s1 += __shfl_xor_sync(0xffffffffu, s1, off);
            s2 += __shfl_xor_sync(0xffffffffu, s2, off);
        }
        if (row < N) {
            float* hp = h + (size_t)row * FOUT + lane * VEC;
            if constexpr (VEC == 4) {
                *(float4*)hp = make_float4(acc[r][0], acc[r][1], acc[r][2], acc[r][3]);
            } else if constexpr (VEC == 2) {
                *(float2*)hp = make_float2(acc[r][0], acc[r][1]);
            } else {
                *hp = acc[r][0];
            }
            if (lane == 0) { as_out[row] = s1; ad_out[row] = s2; }
        }
    }
}

// ---------------------------------------------------------------------------
// Post GEMM: out = relu(x @ W + b)
// ---------------------------------------------------------------------------
template <int FIN, int FOUT, int KC>
__global__ void __launch_bounds__(256) post_gemm_k(
    const float* __restrict__ x, const float* __restrict__ W,
    const float* __restrict__ b, float* __restrict__ out, int N)
{
    constexpr int VEC = FOUT / 32;
    constexpr int XR  = FIN / 32;
    constexpr int NCH = FIN / KC;
    __shared__ float sW[KC * FOUT];

    const int warp = threadIdx.x >> 5;
    const int lane = threadIdx.x & 31;
    const int row0 = (blockIdx.x * 8 + warp) * 4;

    float xr[4][XR];
#pragma unroll
    for (int r = 0; r < 4; r++) {
        const float* xp = x + (size_t)(row0 + r) * FIN;
#pragma unroll
        for (int i = 0; i < XR; i++)
            xr[r][i] = (row0 + r < N) ? xp[lane + 32 * i] : 0.f;
    }

    float acc[4][VEC];
#pragma unroll
    for (int r = 0; r < 4; r++)
#pragma unroll
        for (int v = 0; v < VEC; v++) acc[r][v] = 0.f;

#pragma unroll
    for (int c = 0; c < NCH; c++) {
        __syncthreads();
        for (int i = threadIdx.x; i < KC * FOUT; i += 256)
            sW[i] = W[c * KC * FOUT + i];
        __syncthreads();
#pragma unroll
        for (int kk = 0; kk < KC; kk++) {
            const int k = c * KC + kk;
            float wv[VEC];
            const float* wp = sW + kk * FOUT + lane * VEC;
            if constexpr (VEC == 4) {
                float4 t = *(const float4*)wp;
                wv[0] = t.x; wv[1] = t.y; wv[2] = t.z; wv[3] = t.w;
            } else if constexpr (VEC == 2) {
                float2 t = *(const float2*)wp;
                wv[0] = t.x; wv[1] = t.y;
            } else {
                wv[0] = *wp;
            }
#pragma unroll
            for (int r = 0; r < 4; r++) {
                float xk = __shfl_sync(0xffffffffu, xr[r][k >> 5], k & 31);
#pragma unroll
                for (int v = 0; v < VEC; v++)
                    acc[r][v] = fmaf(xk, wv[v], acc[r][v]);
            }
        }
    }

    float bv[VEC];
#pragma unroll
    for (int v = 0; v < VEC; v++) bv[v] = b[lane * VEC + v];
#pragma unroll
    for (int r = 0; r < 4; r++) {
        int row = row0 + r;
        if (row < N) {
            float* op = out + (size_t)row * FOUT + lane * VEC;
            float o[VEC];
#pragma unroll
            for (int v = 0; v < VEC; v++) o[v] = fmaxf(acc[r][v] + bv[v], 0.f);
            if constexpr (VEC == 4) {
                *(float4*)op = make_float4(o[0], o[1], o[2], o[3]);
            } else if constexpr (VEC == 2) {
                *(float2*)op = make_float2(o[0], o[1]);
            } else {
                *op = o[0];
            }
        }
    }
}

// ---------------------------------------------------------------------------
// Softmax aggregation: warp per dst node, single pass (self-score stabilizer).
// FINISH: apply bias+relu (feature array is post-GEMM h).  Else raw weighted
// mean (feature array is pre-GEMM x).
// ---------------------------------------------------------------------------
__device__ __forceinline__ float lrelu(float e) { return e > 0.f ? e : 0.2f * e; }

template <int F, bool FINISH>
__global__ void __launch_bounds__(256) gat_agg_k(
    const int* __restrict__ rp, const int* __restrict__ col,
    const float* __restrict__ g, const float* __restrict__ as,
    const float* __restrict__ ad, const float* __restrict__ bias,
    float* __restrict__ out, int N)
{
    constexpr int VEC = F / 32;
    int node = blockIdx.x * 8 + (threadIdx.x >> 5);
    if (node >= N) return;
    int lane = threadIdx.x & 31;
    int beg = rp[node], end = rp[node + 1];
    float add = ad[node];
    float m = lrelu(as[node] + add);     // self-loop score: denom >= 1

    float acc[VEC];
#pragma unroll
    for (int v = 0; v < VEC; v++) acc[v] = 0.f;
    float s = 0.f;
    int j = beg;
    for (; j + 4 <= end; j += 4) {
        int s0 = col[j], s1 = col[j + 1], s2 = col[j + 2], s3 = col[j + 3];
        float w0 = __expf(lrelu(as[s0] + add) - m);
        float w1 = __expf(lrelu(as[s1] + add) - m);
        float w2 = __expf(lrelu(as[s2] + add) - m);
        float w3 = __expf(lrelu(as[s3] + add) - m);
        s += (w0 + w1) + (w2 + w3);
        const float* p0 = g + (size_t)s0 * F + lane * VEC;
        const float* p1 = g + (size_t)s1 * F + lane * VEC;
        const float* p2 = g + (size_t)s2 * F + lane * VEC;
        const float* p3 = g + (size_t)s3 * F + lane * VEC;
        if constexpr (VEC == 4) {
            float4 t0 = *(const float4*)p0;
            float4 t1 = *(const float4*)p1;
            float4 t2 = *(const float4*)p2;
            float4 t3 = *(const float4*)p3;
            acc[0] = fmaf(w0, t0.x, acc[0]); acc[1] = fmaf(w0, t0.y, acc[1]);
            acc[2] = fmaf(w0, t0.z, acc[2]); acc[3] = fmaf(w0, t0.w, acc[3]);
            acc[0] = fmaf(w1, t1.x, acc[0]); acc[1] = fmaf(w1, t1.y, acc[1]);
            acc[2] = fmaf(w1, t1.z, acc[2]); acc[3] = fmaf(w1, t1.w, acc[3]);
            acc[0] = fmaf(w2, t2.x, acc[0]); acc[1] = fmaf(w2, t2.y, acc[1]);
            acc[2] = fmaf(w2, t2.z, acc[2]); acc[3] = fmaf(w2, t2.w, acc[3]);
            acc[0] = fmaf(w3, t3.x, acc[0]); acc[1] = fmaf(w3, t3.y, acc[1]);
            acc[2] = fmaf(w3, t3.z, acc[2]); acc[3] = fmaf(w3, t3.w, acc[3]);
        } else if constexpr (VEC == 2) {
            float2 t0 = *(const float2*)p0;
            float2 t1 = *(const float2*)p1;
            float2 t2 = *(const float2*)p2;
            float2 t3 = *(const float2*)p3;
            acc[0] = fmaf(w0, t0.x, acc[0]); acc[1] = fmaf(w0, t0.y, acc[1]);
            acc[0] = fmaf(w1, t1.x, acc[0]); acc[1] = fmaf(w1, t1.y, acc[1]);
            acc[0] = fmaf(w2, t2.x, acc[0]); acc[1] = fmaf(w2, t2.y, acc[1]);
            acc[0] = fmaf(w3, t3.x, acc[0]); acc[1] = fmaf(w3, t3.y, acc[1]);
        } else {
            acc[0] = fmaf(w0, *p0, acc[0]);
            acc[0] = fmaf(w1, *p1, acc[0]);
            acc[0] = fmaf(w2, *p2, acc[0]);
            acc[0] = fmaf(w3, *p3, acc[0]);
        }
    }
    for (; j < end; ++j) {
        int src = col[j];
        float w = __expf(lrelu(as[src] + add) - m);
        s += w;
        const float* hp = g + (size_t)src * F + lane * VEC;
#pragma unroll
        for (int v = 0; v < VEC; v++)
            acc[v] = fmaf(w, hp[v], acc[v]);
    }

    float inv = 1.f / s;
    float* op = out + (size_t)node * F + lane * VEC;
    float o[VEC];
#pragma unroll
    for (int v = 0; v < VEC; v++) {
        if constexpr (FINISH)
            o[v] = fmaxf(acc[v] * inv + bias[lane * VEC + v], 0.f);
        else
            o[v] = acc[v] * inv;
    }
    if constexpr (VEC == 4) {
        *(float4*)op = make_float4(o[0], o[1], o[2], o[3]);
    } else if constexpr (VEC == 2) {
        *(float2*)op = make_float2(o[0], o[1]);
    } else {
        *op = o[0];
    }
}

// ---------------------------------------------------------------------------
// Final FC: out = x @ fc_W + fc_b   ([N,128] @ [128,16])
// ---------------------------------------------------------------------------
__global__ void __launch_bounds__(256) fc_k(
    const float* __restrict__ x, const float* __restrict__ W,
    const float* __restrict__ b, float* __restrict__ out, int N)
{
    __shared__ float sW[128 * 16];
    for (int i = threadIdx.x; i < 128 * 16; i += 256) sW[i] = W[i];
    __syncthreads();
    int warp = threadIdx.x >> 5, lane = threadIdx.x & 31;
    int row = blockIdx.x * 8 + warp;
    float xr[4];
    const float* xp = x + (size_t)row * 128;
#pragma unroll
    for (int i = 0; i < 4; i++) xr[i] = (row < N) ? xp[lane + 32 * i] : 0.f;
    float acc = 0.f;
#pragma unroll
    for (int k = 0; k < 128; k++) {
        float xk = __shfl_sync(0xffffffffu, xr[k >> 5], k & 31);
        acc = fmaf(xk, sW[k * 16 + (lane & 15)], acc);
    }
    if (row < N && lane < 16) out[(size_t)row * 16 + lane] = acc + b[lane];
}

// ---------------------------------------------------------------------------
// Host launcher
// ---------------------------------------------------------------------------
extern "C" void kernel_launch(void* const* d_in, const int* in_sizes, int n_in,
                              void* d_out, int out_size)
{
    const float* x   = (const float*)d_in[0];
    const void*  ei  = d_in[1];
    const float* W[4]  = {(const float*)d_in[2],  (const float*)d_in[6],
                          (const float*)d_in[10], (const float*)d_in[14]};
    const float* As[4] = {(const float*)d_in[3],  (const float*)d_in[7],
                          (const float*)d_in[11], (const float*)d_in[15]};
    const float* Ad[4] = {(const float*)d_in[4],  (const float*)d_in[8],
                          (const float*)d_in[12], (const float*)d_in[16]};
    const float* B[4]  = {(const float*)d_in[5],  (const float*)d_in[9],
                          (const float*)d_in[13], (const float*)d_in[17]};
    const float* fcW = (const float*)d_in[18];
    const float* fcB = (const float*)d_in[19];

    int N = in_sizes[0] / 128;
    int E = in_sizes[1] / 2;
    int M = E + N;
    int nb = (N + SCANB - 1) / SCANB;

    float *h0, *h1, *as_, *ad_, *us, *ud;
    int *rp, *cnt, *cur, *col, *psum;
    cudaGetSymbolAddress((void**)&h0,   g_h0);
    cudaGetSymbolAddress((void**)&h1,   g_h1);
    cudaGetSymbolAddress((void**)&as_,  g_as);
    cudaGetSymbolAddress((void**)&ad_,  g_ad);
    cudaGetSymbolAddress((void**)&us,   g_us);
    cudaGetSymbolAddress((void**)&ud,   g_ud);
    cudaGetSymbolAddress((void**)&rp,   g_rp);
    cudaGetSymbolAddress((void**)&cnt,  g_cnt);
    cudaGetSymbolAddress((void**)&cur,  g_cur);
    cudaGetSymbolAddress((void**)&col,  g_col);
    cudaGetSymbolAddress((void**)&psum, g_psum);

    // --- dtype sniff + CSR build ---
    detect_k<<<1, 32>>>((const int*)ei);
    zero_cnt_k<<<(N + 255) / 256, 256>>>(cnt, N);
    count_k<<<(M + 255) / 256, 256>>>(ei, E, N, cnt);
    scan1_k<<<nb, SCANB>>>(cnt, psum, N);
    scan2_k<<<1, SCANB>>>(psum, nb, rp, N);
    scan3_k<<<nb, SCANB>>>(cnt, psum, rp, cur, N);
    scatter_k<<<(M + 255) / 256, 256>>>(ei, E, N, cur, col);

    int gemm_grid = (N + 31) / 32;
    int agg_grid  = (N + 7) / 8;

    // --- Layer 0: 128 -> 32  (GEMM then aggregate: FOUT < FIN) ---
    gat_gemm_k<128, 32, 64><<<gemm_grid, 256>>>(x, W[0], As[0], Ad[0], h0, as_, ad_, N);
    gat_agg_k<32, true><<<agg_grid, 256>>>(rp, col, h0, as_, ad_, B[0], h1, N);

    // --- Layer 1: 32 -> 64  (aggregate then GEMM: FIN < FOUT) ---
    wa_k<32, 64><<<1, 256>>>(W[1], As[1], Ad[1], us, ud);
    score_k<32><<<agg_grid, 256>>>(h1, us, ud, as_, ad_, N);
    gat_agg_k<32, false><<<agg_grid, 256>>>(rp, col, h1, as_, ad_, nullptr, h0, N);
    post_gemm_k<32, 64, 32><<<gemm_grid, 256>>>(h0, W[1], B[1], h1, N);

    // --- Layer 2: 64 -> 128  (aggregate then GEMM) ---
    wa_k<64, 128><<<1, 256>>>(W[2], As[2], Ad[2], us, ud);
    score_k<64><<<agg_grid, 256>>>(h1, us, ud, as_, ad_, N);
    gat_agg_k<64, false><<<agg_grid, 256>>>(rp, col, h1, as_, ad_, nullptr, h0, N);
    post_gemm_k<64, 128, 64><<<gemm_grid, 256>>>(h0, W[2], B[2], h1, N);

    // --- Layer 3: 128 -> 128 (GEMM then aggregate) ---
    gat_gemm_k<128, 128, 64><<<gemm_grid, 256>>>(h1, W[3], As[3], Ad[3], h0, as_, ad_, N);
    gat_agg_k<128, true><<<agg_grid, 256>>>(rp, col, h0, as_, ad_, B[3], h1, N);

    // --- FC: 128 -> 16 ---
    fc_k<<<agg_grid, 256>>>(h1, fcW, fcB, (float*)d_out, N);
}

// round 11
// speedup vs baseline: 1.1849x; 1.0053x over previous
#include <cuda_runtime.h>
#include <cuda_fp16.h>
#include <cstdint>

// ---------------------------------------------------------------------------
// GAT (4 layers) + FC on GB300.
//   - CSR by destination built once (fast 3-stage scan), col + dst arrays.
//   - Edge softmax weights precomputed edge-parallel (coalesced, high MLP),
//     self-loop score as stabilizer (no segment-max pass).
//   - Aggregation gathers fp16 feature rows; int4/float4 col+w loads.
//   - Aggregate on the cheaper side of the GEMM (associativity trick for
//     scores: u = W@a).
// ---------------------------------------------------------------------------

#define MAXN 50176            // >= 50000, padded (multiple of 256)
#define MAXEL 1703936         // >= E + N
#define SCANB 256

__device__ float  g_h0[(size_t)MAXN * 128];
__device__ float  g_h1[(size_t)MAXN * 128];
__device__ __half g_ha[(size_t)MAXN * 128];
__device__ __half g_hb[(size_t)MAXN * 128];
__device__ float  g_as[MAXN];
__device__ float  g_ad[MAXN];
__device__ float2 g_pair[MAXN];
__device__ float  g_w[MAXEL];
__device__ float  g_us[128];
__device__ float  g_ud[128];
__device__ int    g_rp[MAXN + 1];
__device__ int    g_cnt[MAXN];
__device__ int    g_cur[MAXN];
__device__ int    g_col[MAXEL];
__device__ int    g_dst[MAXEL];
__device__ int    g_psum[MAXN / SCANB + 1];
__device__ int    g_is64;

__device__ __forceinline__ float lrelu(float e) { return e > 0.f ? e : 0.2f * e; }

// ---------------------------------------------------------------------------
// dtype detect (JAX demotes int64->int32 without x64)
// ---------------------------------------------------------------------------
__global__ void detect_k(const int* __restrict__ w) {
    int lane = threadIdx.x;
    int bad = (w[lane * 2 + 1] != 0);
    unsigned any = __ballot_sync(0xffffffffu, bad);
    if (lane == 0) g_is64 = (any == 0u);
}

__device__ __forceinline__ int load_idx(const void* ei, size_t pos) {
    if (g_is64) return (int)((const long long*)ei)[pos];
    return ((const int*)ei)[pos];
}

// ---------------------------------------------------------------------------
// CSR build
// ---------------------------------------------------------------------------
__global__ void zero_cnt_k(int* cnt, int n) {
    int i = blockIdx.x * blockDim.x + threadIdx.x;
    if (i < n) cnt[i] = 0;
}

__global__ void count_k(const void* __restrict__ ei, int E, int N, int* cnt) {
    int i = blockIdx.x * blockDim.x + threadIdx.x;
    int M = E + N;
    if (i >= M) return;
    int d = (i < E) ? load_idx(ei, (size_t)E + i) : (i - E);
    if (d < 0 || d >= N) d = 0;
    atomicAdd(&cnt[d], 1);
}

__global__ void scan1_k(const int* __restrict__ cnt, int* psum, int n) {
    __shared__ int ss[8];
    int i = blockIdx.x * SCANB + threadIdx.x;
    int v = (i < n) ? cnt[i] : 0;
#pragma unroll
    for (int off = 16; off; off >>= 1) v += __shfl_xor_sync(0xffffffffu, v, off);
    if ((threadIdx.x & 31) == 0) ss[threadIdx.x >> 5] = v;
    __syncthreads();
    if (threadIdx.x == 0) {
        int t = 0;
#pragma unroll
        for (int k = 0; k < 8; k++) t += ss[k];
        psum[blockIdx.x] = t;
    }
}

__global__ void scan2_k(int* psum, int nb, int* rp, int n) {
    __shared__ int ss[SCANB];
    int tid = threadIdx.x;
    int v = (tid < nb) ? psum[tid] : 0;
    ss[tid] = v;
    __syncthreads();
#pragma unroll
    for (int off = 1; off < SCANB; off <<= 1) {
        int t = (tid >= off) ? ss[tid - off] : 0;
        __syncthreads();
        ss[tid] += t;
        __syncthreads();
    }
    if (tid < nb) psum[tid] = ss[tid] - v;
    if (tid == SCANB - 1) rp[n] = ss[SCANB - 1];
}

__global__ void scan3_k(const int* __restrict__ cnt, const int* __restrict__ psum,
                        int* rp, int* cur, int n) {
    __shared__ int ss[SCANB];
    int tid = threadIdx.x;
    int i = blockIdx.x * SCANB + tid;
    int v = (i < n) ? cnt[i] : 0;
    ss[tid] = v;
    __syncthreads();
#pragma unroll
    for (int off = 1; off < SCANB; off <<= 1) {
        int t = (tid >= off) ? ss[tid - off] : 0;
        __syncthreads();
        ss[tid] += t;
        __syncthreads();
    }
    if (i < n) {
        int r = ss[tid] - v + psum[blockIdx.x];
        rp[i] = r;
        cur[i] = r;
    }
}

__global__ void scatter_k(const void* __restrict__ ei, int E, int N,
                          int* cur, int* __restrict__ col, int* __restrict__ dst) {
    int i = blockIdx.x * blockDim.x + threadIdx.x;
    int M = E + N;
    if (i >= M) return;
    int d, s;
    if (i < E) {
        d = load_idx(ei, (size_t)E + i);
        s = load_idx(ei, (size_t)i);
    } else {
        d = i - E;
        s = d;
    }
    if (d < 0 || d >= N) d = 0;
    if (s < 0 || s >= N) s = 0;
    int p = atomicAdd(&cur[d], 1);
    if (p >= 0 && p < MAXEL) { col[p] = s; dst[p] = d; }
}

// ---------------------------------------------------------------------------
// u = W @ a  (tiny). One block.
// ---------------------------------------------------------------------------
template <int FIN, int FOUT>
__global__ void wa_k(const float* __restrict__ W, const float* __restrict__ a_s,
                     const float* __restrict__ a_d,
                     float* __restrict__ us, float* __restrict__ ud) {
    int i = threadIdx.x;
    if (i >= FIN) return;
    float s1 = 0.f, s2 = 0.f;
#pragma unroll 4
    for (int j = 0; j < FOUT; j++) {
        float w = W[i * FOUT + j];
        s1 = fmaf(w, a_s[j], s1);
        s2 = fmaf(w, a_d[j], s2);
    }
    us[i] = s1;
    ud[i] = s2;
}

// ---------------------------------------------------------------------------
// Scores: alpha_s[n] = x[n,:]@us, alpha_d[n] = x[n,:]@ud. Warp per row.
// ---------------------------------------------------------------------------
template <int F>
__global__ void __launch_bounds__(256) score_k(
    const float* __restrict__ x, const float* __restrict__ us,
    const float* __restrict__ ud, float* __restrict__ as_out,
    float* __restrict__ ad_out, int N)
{
    int node = blockIdx.x * 8 + (threadIdx.x >> 5);
    if (node >= N) return;
    int lane = threadIdx.x & 31;
    const float* xp = x + (size_t)node * F;
    float s1 = 0.f, s2 = 0.f;
#pragma unroll
    for (int i = lane; i < F; i += 32) {
        float xv = xp[i];
        s1 = fmaf(xv, us[i], s1);
        s2 = fmaf(xv, ud[i], s2);
    }
#pragma unroll
    for (int off = 16; off; off >>= 1) {
        s1 += __shfl_xor_sync(0xffffffffu, s1, off);
        s2 += __shfl_xor_sync(0xffffffffu, s2, off);
    }
    if (lane == 0) { as_out[node] = s1; ad_out[node] = s2; }
}

// ---------------------------------------------------------------------------
// Per-node (ad, m) pair; m = self-loop score (softmax stabilizer, denom >= 1)
// ---------------------------------------------------------------------------
__global__ void pair_k(const float* __restrict__ as, const float* __restrict__ ad,
                       float2* __restrict__ pair, int N) {
    int i = blockIdx.x * blockDim.x + threadIdx.x;
    if (i >= N) return;
    float a = ad[i];
    pair[i] = make_float2(a, lrelu(as[i] + a));
}

// ---------------------------------------------------------------------------
// Edge weights, edge-parallel: w[j] = exp(lrelu(as[src]+ad[dst]) - m[dst])
// Two edges per thread (int2 loads) for MLP.
// ---------------------------------------------------------------------------
__global__ void __launch_bounds__(256) weight_k(
    const int* __restrict__ col, const int* __restrict__ dst,
    const float* __restrict__ as, const float2* __restrict__ pair,
    float* __restrict__ w, int M)
{
    int j = (blockIdx.x * blockDim.x + threadIdx.x) * 2;
    if (j + 1 < M) {
        int2 c2 = *(const int2*)(col + j);
        int2 d2 = *(const int2*)(dst + j);
        float a0 = as[c2.x], a1 = as[c2.y];
        float2 p0 = pair[d2.x], p1 = pair[d2.y];
        float2 o;
        o.x = __expf(lrelu(a0 + p0.x) - p0.y);
        o.y = __expf(lrelu(a1 + p1.x) - p1.y);
        *(float2*)(w + j) = o;
    } else if (j < M) {
        int s = col[j];
        float2 p = pair[dst[j]];
        w[j] = __expf(lrelu(as[s] + p.x) - p.y);
    }
}

// ---------------------------------------------------------------------------
// fp16 gather + weighted accumulate helper
// ---------------------------------------------------------------------------
template <int F>
__device__ __forceinline__ void gfma(const __half* __restrict__ hh, int src,
                                     int lane, float wt, float* acc) {
    constexpr int VEC = F / 32;
    const __half* p = hh + (size_t)src * F + lane * VEC;
    if constexpr (VEC == 4) {
        uint2 t = *(const uint2*)p;
        __half2 a = *reinterpret_cast<__half2*>(&t.x);
        __half2 b = *reinterpret_cast<__half2*>(&t.y);
        float2 fa = __half22float2(a), fb = __half22float2(b);
        acc[0] = fmaf(wt, fa.x, acc[0]); acc[1] = fmaf(wt, fa.y, acc[1]);
        acc[2] = fmaf(wt, fb.x, acc[2]); acc[3] = fmaf(wt, fb.y, acc[3]);
    } else if constexpr (VEC == 2) {
        float2 f = __half22float2(*(const __half2*)p);
        acc[0] = fmaf(wt, f.x, acc[0]); acc[1] = fmaf(wt, f.y, acc[1]);
    } else {
        acc[0] = fmaf(wt, __half2float(*p), acc[0]);
    }
}

// ---------------------------------------------------------------------------
// Aggregation: warp per dst node. Weights precomputed. int4/float4 index loads.
// FINISH: apply bias + relu. out32 always written; out16 optionally.
// ---------------------------------------------------------------------------
template <int F, bool FINISH>
__global__ void __launch_bounds__(256) agg_k(
    const int* __restrict__ rp, const int* __restrict__ col,
    const float* __restrict__ w, const __half* __restrict__ hh,
    const float* __restrict__ bias,
    float* __restrict__ out32, __half* __restrict__ out16, int N)
{
    constexpr int VEC = F / 32;
    int node = blockIdx.x * 8 + (threadIdx.x >> 5);
    if (node >= N) return;
    int lane = threadIdx.x & 31;
    int beg = rp[node], end = rp[node + 1];

    float acc[VEC];
#pragma unroll
    for (int v = 0; v < VEC; v++) acc[v] = 0.f;
    float s = 0.f;

    int j = beg;
    int jal = min(end, (beg + 3) & ~3);
    for (; j < jal; ++j) {
        float wt = w[j];
        s += wt;
        gfma<F>(hh, col[j], lane, wt, acc);
    }
    for (; j + 4 <= end; j += 4) {
        int4   c4 = *(const int4*)(col + j);
        float4 w4 = *(const float4*)(w + j);
        s += (w4.x + w4.y) + (w4.z + w4.w);
        gfma<F>(hh, c4.x, lane, w4.x, acc);
        gfma<F>(hh, c4.y, lane, w4.y, acc);
        gfma<F>(hh, c4.z, lane, w4.z, acc);
        gfma<F>(hh, c4.w, lane, w4.w, acc);
    }
    for (; j < end; ++j) {
        float wt = w[j];
        s += wt;
        gfma<F>(hh, col[j], lane, wt, acc);
    }

    float inv = 1.f / s;
    float o[VEC];
#pragma unroll
    for (int v = 0; v < VEC; v++) {
        if constexpr (FINISH)
            o[v] = fmaxf(acc[v] * inv + bias[lane * VEC + v], 0.f);
        else
            o[v] = acc[v] * inv;
    }
    float* op = out32 + (size_t)node * F + lane * VEC;
    if constexpr (VEC == 4)      *(float4*)op = make_float4(o[0], o[1], o[2], o[3]);
    else if constexpr (VEC == 2) *(float2*)op = make_float2(o[0], o[1]);
    else                         *op = o[0];

    if (out16) {
        __half* hp = out16 + (size_t)node * F + lane * VEC;
        if constexpr (VEC == 4) {
            uint2 t;
            *reinterpret_cast<__half2*>(&t.x) = __floats2half2_rn(o[0], o[1]);
            *reinterpret_cast<__half2*>(&t.y) = __floats2half2_rn(o[2], o[3]);
            *(uint2*)hp = t;
        } else if constexpr (VEC == 2) {
            *(__half2*)hp = __floats2half2_rn(o[0], o[1]);
        } else {
            *hp = __float2half_rn(o[0]);
        }
    }
}

// ---------------------------------------------------------------------------
// Fused GEMM: h16 = fp16(x @ W) ; alpha_s/alpha_d epilogue. Warp: 4 rows.
// ---------------------------------------------------------------------------
template <int FIN, int FOUT, int KC>
__global__ void __launch_bounds__(256) gat_gemm_k(
    const float* __restrict__ x, const float* __restrict__ W,
    const float* __restrict__ avs, const float* __restrict__ avd,
    __half* __restrict__ h16, float* __restrict__ as_out,
    float* __restrict__ ad_out, int N)
{
    constexpr int VEC = FOUT / 32;
    constexpr int XR  = FIN / 32;
    constexpr int NCH = FIN / KC;
    __shared__ float sW[KC * FOUT];

    const int warp = threadIdx.x >> 5;
    const int lane = threadIdx.x & 31;
    const int row0 = (blockIdx.x * 8 + warp) * 4;

    float xr[4][XR];
#pragma unroll
    for (int r = 0; r < 4; r++) {
        const float* xp = x + (size_t)(row0 + r) * FIN;
#pragma unroll
        for (int i = 0; i < XR; i++)
            xr[r][i] = (row0 + r < N) ? xp[lane + 32 * i] : 0.f;
    }

    float acc[4][VEC];
#pragma unroll
    for (int r = 0; r < 4; r++)
#pragma unroll
        for (int v = 0; v < VEC; v++) acc[r][v] = 0.f;

#pragma unroll
    for (int c = 0; c < NCH; c++) {
        __syncthreads();
        for (int i = threadIdx.x; i < KC * FOUT; i += 256)
            sW[i] = W[c * KC * FOUT + i];
        __syncthreads();
#pragma unroll
        for (int kk = 0; kk < KC; kk++) {
            const int k = c * KC + kk;
            float wv[VEC];
            const float* wp = sW + kk * FOUT + lane * VEC;
            if constexpr (VEC == 4) {
                float4 t = *(const float4*)wp;
                wv[0] = t.x; wv[1] = t.y; wv[2] = t.z; wv[3] = t.w;
            } else if constexpr (VEC == 2) {
                float2 t = *(const float2*)wp;
                wv[0] = t.x; wv[1] = t.y;
            } else {
                wv[0] = *wp;
            }
#pragma unroll
            for (int r = 0; r < 4; r++) {
                float xk = __shfl_sync(0xffffffffu, xr[r][k >> 5], k & 31);
#pragma unroll
                for (int v = 0; v < VEC; v++)
                    acc[r][v] = fmaf(xk, wv[v], acc[r][v]);
            }
        }
    }

    float av1[VEC], av2[VEC];
#pragma unroll
    for (int v = 0; v < VEC; v++) {
        av1[v] = avs[lane * VEC + v];
        av2[v] = avd[lane * VEC + v];
    }
#pragma unroll
    for (int r = 0; r < 4; r++) {
        int row = row0 + r;
        float s1 = 0.f, s2 = 0.f;
#pragma unroll
        for (int v = 0; v < VEC; v++) {
            s1 = fmaf(acc[r][v], av1[v], s1);
            s2 = fmaf(acc[r][v], av2[v], s2);
        }
#pragma unroll
        for (int off = 16; off; off >>= 1) {
            s1 += __shfl_xor_sync(0xffffffffu, s1, off);
            s2 += __shfl_xor_sync(0xffffffffu, s2, off);
        }
        if (row < N) {
            __half* hp = h16 + (size_t)row * FOUT + lane * VEC;
            if constexpr (VEC == 4) {
                uint2 t;
                *reinterpret_cast<__half2*>(&t.x) = __floats2half2_rn(acc[r][0], acc[r][1]);
                *reinterpret_cast<__half2*>(&t.y) = __floats2half2_rn(acc[r][2], acc[r][3]);
                *(uint2*)hp = t;
            } else if constexpr (VEC == 2) {
                *(__half2*)hp = __floats2half2_rn(acc[r][0], acc[r][1]);
            } else {
                *hp = __float2half_rn(acc[r][0]);
            }
            if (lane == 0) { as_out[row] = s1; ad_out[row] = s2; }
        }
    }
}

// ---------------------------------------------------------------------------
// Post GEMM: relu(x @ W + b) -> fp32 out (+ optional fp16 copy)
// ---------------------------------------------------------------------------
template <int FIN, int FOUT, int KC>
__global__ void __launch_bounds__(256) post_gemm_k(
    const float* __restrict__ x, const float* __restrict__ W,
    const float* __restrict__ b, float* __restrict__ out32,
    __half* __restrict__ out16, int N)
{
    constexpr int VEC = FOUT / 32;
    constexpr int XR  = FIN / 32;
    constexpr int NCH = FIN / KC;
    __shared__ float sW[KC * FOUT];

    const int warp = threadIdx.x >> 5;
    const int lane = threadIdx.x & 31;
    const int row0 = (blockIdx.x * 8 + warp) * 4;

    float xr[4][XR];
#pragma unroll
    for (int r = 0; r < 4; r++) {
        const float* xp = x + (size_t)(row0 + r) * FIN;
#pragma unroll
        for (int i = 0; i < XR; i++)
            xr[r][i] = (row0 + r < N) ? xp[lane + 32 * i] : 0.f;
    }

    float acc[4][VEC];
#pragma unroll
    for (int r = 0; r < 4; r++)
#pragma unroll
        for (int v = 0; v < VEC; v++) acc[r][v] = 0.f;

#pragma unroll
    for (int c = 0; c < NCH; c++) {
        __syncthreads();
        for (int i = threadIdx.x; i < KC * FOUT; i += 256)
            sW[i] = W[c * KC * FOUT + i];
        __syncthreads();
#pragma unroll
        for (int kk = 0; kk < KC; kk++) {
            const int k = c * KC + kk;
            float wv[VEC];
            const float* wp = sW + kk * FOUT + lane * VEC;
            if constexpr (VEC == 4) {
                float4 t = *(const float4*)wp;
                wv[0] = t.x; wv[1] = t.y; wv[2] = t.z; wv[3] = t.w;
            } else if constexpr (VEC == 2) {
                float2 t = *(const float2*)wp;
                wv[0] = t.x; wv[1] = t.y;
            } else {
                wv[0] = *wp;
            }
#pragma unroll
            for (int r = 0; r < 4; r++) {
                float xk = __shfl_sync(0xffffffffu, xr[r][k >> 5], k & 31);
#pragma unroll
                for (int v = 0; v < VEC; v++)
                    acc[r][v] = fmaf(xk, wv[v], acc[r][v]);
            }
        }
    }

    float bv[VEC];
#pragma unroll
    for (int v = 0; v < VEC; v++) bv[v] = b[lane * VEC + v];
#pragma unroll
    for (int r = 0; r < 4; r++) {
        int row = row0 + r;
        if (row < N) {
            float o[VEC];
#pragma unroll
            for (int v = 0; v < VEC; v++) o[v] = fmaxf(acc[r][v] + bv[v], 0.f);
            float* op = out32 + (size_t)row * FOUT + lane * VEC;
            if constexpr (VEC == 4)      *(float4*)op = make_float4(o[0], o[1], o[2], o[3]);
            else if constexpr (VEC == 2) *(float2*)op = make_float2(o[0], o[1]);
            else                         *op = o[0];
            if (out16) {
                __half* hp = out16 + (size_t)row * FOUT + lane * VEC;
                if constexpr (VEC == 4) {
                    uint2 t;
                    *reinterpret_cast<__half2*>(&t.x) = __floats2half2_rn(o[0], o[1]);
                    *reinterpret_cast<__half2*>(&t.y) = __floats2half2_rn(o[2], o[3]);
                    *(uint2*)hp = t;
                } else if constexpr (VEC == 2) {
                    *(__half2*)hp = __floats2half2_rn(o[0], o[1]);
                } else {
                    *hp = __float2half_rn(o[0]);
                }
            }
        }
    }
}

// ---------------------------------------------------------------------------
// Final FC: out = x @ fc_W + fc_b   ([N,128] @ [128,16])
// ---------------------------------------------------------------------------
__global__ void __launch_bounds__(256) fc_k(
    const float* __restrict__ x, const float* __restrict__ W,
    const float* __restrict__ b, float* __restrict__ out, int N)
{
    __shared__ float sW[128 * 16];
    for (int i = threadIdx.x; i < 128 * 16; i += 256) sW[i] = W[i];
    __syncthreads();
    int warp = threadIdx.x >> 5, lane = threadIdx.x & 31;
    int row = blockIdx.x * 8 + warp;
    float xr[4];
    const float* xp = x + (size_t)row * 128;
#pragma unroll
    for (int i = 0; i < 4; i++) xr[i] = (row < N) ? xp[lane + 32 * i] : 0.f;
    float acc = 0.f;
#pragma unroll
    for (int k = 0; k < 128; k++) {
        float xk = __shfl_sync(0xffffffffu, xr[k >> 5], k & 31);
        acc = fmaf(xk, sW[k * 16 + (lane & 15)], acc);
    }
    if (row < N && lane < 16) out[(size_t)row * 16 + lane] = acc + b[lane];
}

// ---------------------------------------------------------------------------
// Host launcher
// ---------------------------------------------------------------------------
extern "C" void kernel_launch(void* const* d_in, const int* in_sizes, int n_in,
                              void* d_out, int out_size)
{
    const float* x   = (const float*)d_in[0];
    const void*  ei  = d_in[1];
    const float* W[4]  = {(const float*)d_in[2],  (const float*)d_in[6],
                          (const float*)d_in[10], (const float*)d_in[14]};
    const float* As[4] = {(const float*)d_in[3],  (const float*)d_in[7],
                          (const float*)d_in[11], (const float*)d_in[15]};
    const float* Ad[4] = {(const float*)d_in[4],  (const float*)d_in[8],
                          (const float*)d_in[12], (const float*)d_in[16]};
    const float* B[4]  = {(const float*)d_in[5],  (const float*)d_in[9],
                          (const float*)d_in[13], (const float*)d_in[17]};
    const float* fcW = (const float*)d_in[18];
    const float* fcB = (const float*)d_in[19];

    int N = in_sizes[0] / 128;
    int E = in_sizes[1] / 2;
    int M = E + N;
    int nb = (N + SCANB - 1) / SCANB;

    float  *h0, *h1, *as_, *ad_, *us, *ud, *w_;
    float2 *pair;
    __half *ha, *hb;
    int *rp, *cnt, *cur, *col, *dstv, *psum;
    cudaGetSymbolAddress((void**)&h0,   g_h0);
    cudaGetSymbolAddress((void**)&h1,   g_h1);
    cudaGetSymbolAddress((void**)&ha,   g_ha);
    cudaGetSymbolAddress((void**)&hb,   g_hb);
    cudaGetSymbolAddress((void**)&as_,  g_as);
    cudaGetSymbolAddress((void**)&ad_,  g_ad);
    cudaGetSymbolAddress((void**)&pair, g_pair);
    cudaGetSymbolAddress((void**)&w_,   g_w);
    cudaGetSymbolAddress((void**)&us,   g_us);
    cudaGetSymbolAddress((void**)&ud,   g_ud);
    cudaGetSymbolAddress((void**)&rp,   g_rp);
    cudaGetSymbolAddress((void**)&cnt,  g_cnt);
    cudaGetSymbolAddress((void**)&cur,  g_cur);
    cudaGetSymbolAddress((void**)&col,  g_col);
    cudaGetSymbolAddress((void**)&dstv, g_dst);
    cudaGetSymbolAddress((void**)&psum, g_psum);

    // --- dtype sniff + CSR build ---
    detect_k<<<1, 32>>>((const int*)ei);
    zero_cnt_k<<<(N + 255) / 256, 256>>>(cnt, N);
    count_k<<<(M + 255) / 256, 256>>>(ei, E, N, cnt);
    scan1_k<<<nb, SCANB>>>(cnt, psum, N);
    scan2_k<<<1, SCANB>>>(psum, nb, rp, N);
    scan3_k<<<nb, SCANB>>>(cnt, psum, rp, cur, N);
    scatter_k<<<(M + 255) / 256, 256>>>(ei, E, N, cur, col, dstv);

    int gemm_grid = (N + 31) / 32;
    int node_grid = (N + 7) / 8;
    int ngrid     = (N + 255) / 256;
    int egrid2    = (M / 2 + 255) / 256 + 1;

    // --- Layer 0: 128 -> 32  (GEMM then aggregate) ---
    gat_gemm_k<128, 32, 64><<<gemm_grid, 256>>>(x, W[0], As[0], Ad[0], ha, as_, ad_, N);
    pair_k<<<ngrid, 256>>>(as_, ad_, pair, N);
    weight_k<<<egrid2, 256>>>(col, dstv, as_, pair, w_, M);
    agg_k<32, true><<<node_grid, 256>>>(rp, col, w_, ha, B[0], h1, hb, N);

    // --- Layer 1: 32 -> 64  (aggregate then GEMM) ---
    wa_k<32, 64><<<1, 256>>>(W[1], As[1], Ad[1], us, ud);
    score_k<32><<<node_grid, 256>>>(h1, us, ud, as_, ad_, N);
    pair_k<<<ngrid, 256>>>(as_, ad_, pair, N);
    weight_k<<<egrid2, 256>>>(col, dstv, as_, pair, w_, M);
    agg_k<32, false><<<node_grid, 256>>>(rp, col, w_, hb, nullptr, h0, nullptr, N);
    post_gemm_k<32, 64, 32><<<gemm_grid, 256>>>(h0, W[1], B[1], h1, ha, N);

    // --- Layer 2: 64 -> 128  (aggregate then GEMM) ---
    wa_k<64, 128><<<1, 256>>>(W[2], As[2], Ad[2], us, ud);
    score_k<64><<<node_grid, 256>>>(h1, us, ud, as_, ad_, N);
    pair_k<<<ngrid, 256>>>(as_, ad_, pair, N);
    weight_k<<<egrid2, 256>>>(col, dstv, as_, pair, w_, M);
    agg_k<64, false><<<node_grid, 256>>>(rp, col, w_, ha, nullptr, h0, nullptr, N);
    post_gemm_k<64, 128, 64><<<gemm_grid, 256>>>(h0, W[2], B[2], h1, nullptr, N);

    // --- Layer 3: 128 -> 128 (GEMM then aggregate) ---
    gat_gemm_k<128, 128, 64><<<gemm_grid, 256>>>(h1, W[3], As[3], Ad[3], ha, as_, ad_, N);
    pair_k<<<ngrid, 256>>>(as_, ad_, pair, N);
    weight_k<<<egrid2, 256>>>(col, dstv, as_, pair, w_, M);
    agg_k<128, true><<<node_grid, 256>>>(rp, col, w_, ha, B[3], h0, nullptr, N);

    // --- FC: 128 -> 16 ---
    fc_k<<<node_grid, 256>>>(h0, fcW, fcB, (float*)d_out, N);
}